// round 16
// baseline (speedup 1.0000x reference)
#include <cuda_runtime.h>
#include <cstdint>

// Problem constants: B=8, S=4096, H=16, E=64, s=64
#define NB 8
#define NH 16
#define NE 64
#define STOT 4096

#define TWO_PI 6.283185307179586476925f

__device__ float g_Mt[NH * 64 * 64];   // TRANSPOSED operator: g_Mt[h][j][n]
__device__ int   g_ready[NH];          // monotone per-head chunk counter (32)

__device__ __forceinline__ uint32_t s2u(const void* p) {
    return (uint32_t)__cvta_generic_to_shared(p);
}
__device__ __forceinline__ void cp16(float* dst, const float* src) {
    asm volatile("cp.async.cg.shared.global [%0], [%1], 16;"
                 :: "r"(s2u(dst)), "l"(src));
}
__device__ __forceinline__ void cp4(float* dst, const float* src) {
    asm volatile("cp.async.ca.shared.global [%0], [%1], 4;"
                 :: "r"(s2u(dst)), "l"(src));
}
__device__ __forceinline__ unsigned long long pack2(float x, float y) {
    unsigned long long r;
    asm("mov.b64 %0, {%1, %2};" : "=l"(r) : "f"(x), "f"(y));
    return r;
}
__device__ __forceinline__ void unpack2(float& x, float& y, unsigned long long v) {
    asm("mov.b64 {%0, %1}, %2;" : "=f"(x), "=f"(y) : "l"(v));
}
__device__ __forceinline__ unsigned long long ffma2(unsigned long long m,
                                                    unsigned long long a,
                                                    unsigned long long c) {
    unsigned long long d;
    asm("fma.rn.f32x2 %0, %1, %2, %3;" : "=l"(d) : "l"(m), "l"(a), "l"(c));
    return d;
}

// ---------------------------------------------------------------------------
// Single fused kernel: 512 blocks = (b,h,e-quarter), 256 threads, 51.2KB smem
// -> 4 CTAs/SM (592 slots >= 512: one wave, handshake deadlock-free).
// 4 independent CTAs per SM keep DRAM streaming while any one CTA is in its
// compute seam (the R15 profile showed DRAM idle ~49% with 2 lock-stepped
// CTAs/SM).
//
// Prologue: stage il=0,1 rows (32x4B cp.async/thread) into builder-dead smem.
// Builder (ALL blocks, chunk c = b*4+eq, 2 n-rows): factored form
//   A[k] = c_k/126 Z[k] conj(w127^{63k}); P[nl][k] = A[k] w126^{kn};
//   M[n][j] = Re sum_k P[nl][k] conj(w127^{kj})  (incremental roots)
// stored TRANSPOSED to g_Mt[h][j][n]; publish via red.release (target 32).
//
// Phase 1: direct-LDG register-tile reduce (16i x 16j per thread at one e).
// Then: all threads spin-acquire g_ready + EARLY M cp.async (overlaps
// partial stores + combine).  Phase 2: fma.rn.f32x2 matvec.
// z_pb (b==0,eq==0): before phase 3.  Phase 3: streaming float4 stores.
// ---------------------------------------------------------------------------
__global__ __launch_bounds__(256, 4)
void fftbias_fused(const float* __restrict__ v,
                   const float* __restrict__ w,
                   const float* __restrict__ o_,
                   float* __restrict__ out,
                   float* __restrict__ out2) {
    const int bx = blockIdx.x;
    const int b  = bx >> 6;
    const int h  = (bx >> 2) & 15;
    const int eq = bx & 3;                 // e-quarter (16 e's)
    const int tid  = threadIdx.x;
    const int lane = tid & 15;             // local e (0..15)
    const int grp  = tid >> 4;             // 0..15
    const int jg   = grp & 3;              // j-group (16 j's)
    const int ig   = grp >> 2;             // i-group (16 i's)

    extern __shared__ float sm[];
    float* vpart = sm;                     // [4 ig][16 e][68] = 4352
    float* upart = sm + 4352;              // [4 jg][16 e][68] = 4352
    float* Msh   = sm + 8704;              // [64 j][64 n]     = 4096
    // staging aliases (dead during builder):
    float* stg0 = upart;                   // il=0: 16 jl x 256 = 4096
    float* stg1 = Msh;                     // il=1: 16 jl x 256 = 4096
    // aliases (live after the reduction):
    float* vs  = vpart;                    // [16][68]
    float* us  = upart;                    // [16][68]
    float* rvs = vpart + 1088;             // [64][16]
    float* rus = vpart + 2112;             // [64][16]
    __shared__ float osh[64];
    __shared__ float zp[64];

    const float* vb = v + ((size_t)b * STOT * NH + h) * NE + eq * 16;
    const float* base = vb + lane;

    // ---- stage il=0 and il=1 rows into builder-dead smem -------------------
    {
        const float* r0 = base + (size_t)(ig * 16 * 64 + jg * 16) * 1024;
        const float* r1 = r0 + (size_t)64 * 1024;
        #pragma unroll
        for (int jl = 0; jl < 16; ++jl)
            cp4(stg0 + jl * 256 + tid, r0 + (size_t)jl * 1024);
        #pragma unroll
        for (int jl = 0; jl < 16; ++jl)
            cp4(stg1 + jl * 256 + tid, r1 + (size_t)jl * 1024);
        asm volatile("cp.async.commit_group;");
    }

    if (tid < 64) osh[tid] = o_[tid];

    // ---- Builder (ALL blocks): chunk c = b*4+eq (2 n-rows of M_h) ----------
    {
        const int c = b * 4 + eq;          // 0..31, rows n = c*2, c*2+1
        // scratch in vpart (dead until phase-1 partial stores)
        float2* root127 = (float2*)vpart;              // 128 f2  @0
        float2* root126 = root127 + 128;               // 128 f2  @256
        float2* Zpart   = root126 + 128;               // 256 f2  @512
        float2* Zsh     = Zpart + 256;                 // 64 f2   @1024
        float2* Ash     = Zsh + 64;                    // 64 f2   @1152
        float*  zsh     = (float*)(Ash + 64);          // 128 f   @1280
        float2* Psh     = (float2*)(zsh + 128);        // 128 f2  @1408
        float*  part    = (float*)(Psh + 128);         // 256 f   @1664..1920

        if (tid < 127) {
            float sv, cv;
            __sincosf(TWO_PI * (float)tid / 127.0f, &sv, &cv);
            root127[tid] = make_float2(cv, sv);
            zsh[tid] = w[h * 127 + tid];
        }
        if (tid < 126) {
            float sv, cv;
            __sincosf(TWO_PI * (float)tid / 126.0f, &sv, &cv);
            root126[tid] = make_float2(cv, sv);
        }
        __syncthreads();

        // Z[k]: 4 u-chunks of 32 in parallel
        {
            const int k  = tid & 63;
            const int uc = tid >> 6;       // 0..3
            const int u0 = uc * 32;
            int m = (k * u0) % 127;
            float zr = 0.f, zi = 0.f;
            #pragma unroll
            for (int s = 0; s < 32; ++s) {
                int u = u0 + s;
                if (u < 127) {
                    float2 rt = root127[m];
                    float zu = zsh[u];
                    zr += zu * rt.x;
                    zi -= zu * rt.y;
                }
                m += k; if (m >= 127) m -= 127;
            }
            Zpart[uc * 64 + k] = make_float2(zr, zi);
        }
        __syncthreads();
        if (tid < 64) {
            float2 p0 = Zpart[tid],       p1 = Zpart[64 + tid];
            float2 p2 = Zpart[128 + tid], p3 = Zpart[192 + tid];
            float zr = p0.x + p1.x + p2.x + p3.x;
            float zi = p0.y + p1.y + p2.y + p3.y;
            // A[k] = c_k/126 * Z[k] * conj(w127^{63k})
            float2 r = root127[(63 * tid) % 127];
            float ck = (tid == 0 || tid == 63) ? (1.0f / 126.0f) : (2.0f / 126.0f);
            Ash[tid] = make_float2(ck * (zr * r.x + zi * r.y),
                                   ck * (zi * r.x - zr * r.y));
        }
        __syncthreads();
        // P[nl][k] = A[k] * w126^{kn}, 2 nl x 64 k = 128 (tid < 128)
        if (tid < 128) {
            const int k = tid & 63, nl = tid >> 6;
            const int n = c * 2 + nl;
            float2 a = Ash[k];
            float2 f = root126[(k * n) % 126];
            Psh[nl * 64 + k] = make_float2(a.x * f.x - a.y * f.y,
                                           a.x * f.y + a.y * f.x);
        }
        __syncthreads();

        // M[n][j] = Re sum_k P[nl][k] conj(w127^{kj}); k-halved, incremental r
        {
            const int ent = tid & 127;
            const int kh  = tid >> 7;      // 0/1
            const int nl  = ent >> 6;
            const int j   = ent & 63;
            float2 r  = root127[(kh * 32 * j) % 127];
            float2 mj = root127[j];
            float acc = 0.f;
            const float2* Pp = Psh + nl * 64 + kh * 32;
            #pragma unroll
            for (int kk = 0; kk < 32; ++kk) {
                float2 Pv = Pp[kk];                // warp-broadcast LDS.64
                acc = fmaf(Pv.x, r.x, acc);
                acc = fmaf(Pv.y, r.y, acc);        // Re(P * conj(r))
                float nx = r.x * mj.x - r.y * mj.y;
                r.y = fmaf(r.x, mj.y, r.y * mj.x);
                r.x = nx;
            }
            part[tid] = acc;
        }
        __syncthreads();
        if (tid < 128) {
            const int nl = tid >> 6, j = tid & 63;
            const int n  = c * 2 + nl;
            g_Mt[h * 4096 + j * 64 + n] = part[tid] + part[tid + 128];
        }
        __syncthreads();                   // scratch dead; STGs issued
        if (tid == 0) {
            asm volatile("red.release.gpu.global.add.s32 [%0], %1;"
                         :: "l"(&g_ready[h]), "r"(1) : "memory");
        }
    }

    // ---- Phase 1: register-tile streaming reduce ---------------------------
    float vacc[16], uacc[16];

    // consume staged il=0,1 rows (own slots only)
    asm volatile("cp.async.wait_group 0;");
    {
        float us0 = 0.f, us1 = 0.f;
        #pragma unroll
        for (int jl = 0; jl < 16; ++jl) {
            float x0 = stg0[jl * 256 + tid];
            float x1 = stg1[jl * 256 + tid];
            vacc[jl] = x0 + x1;
            us0 += x0;
            us1 += x1;
        }
        uacc[0] = us0;
        uacc[1] = us1;
        #pragma unroll
        for (int k = 2; k < 16; ++k) uacc[k] = 0.f;
    }
    __syncthreads();                       // staging regions now reusable

    #pragma unroll
    for (int il = 2; il < 16; ++il) {
        const float* rowp =
            base + (size_t)((ig * 16 + il) * 64 + jg * 16) * 1024;
        #pragma unroll
        for (int jl = 0; jl < 16; ++jl) {
            float x = __ldcs(rowp + (size_t)jl * 1024);
            vacc[jl] += x;                 // v_s[e][jg*16+jl] partial (this ig)
            uacc[il] += x;                 // u_s[e][ig*16+il] partial (this jg)
        }
    }

    // ---- spin (M published ~20us ago) + EARLY M fetch ----------------------
    {
        int rdy;
        do {
            asm volatile("ld.acquire.gpu.global.b32 %0, [%1];"
                         : "=r"(rdy) : "l"(&g_ready[h]) : "memory");
        } while (rdy < 32);
        const float* Msrc = g_Mt + h * 4096;
        cp16(Msh + tid * 16,      Msrc + tid * 16);
        cp16(Msh + tid * 16 + 4,  Msrc + tid * 16 + 4);
        cp16(Msh + tid * 16 + 8,  Msrc + tid * 16 + 8);
        cp16(Msh + tid * 16 + 12, Msrc + tid * 16 + 12);
        asm volatile("cp.async.commit_group;");
    }

    #pragma unroll
    for (int q4 = 0; q4 < 4; ++q4) {       // STS.128
        *(float4*)&vpart[(ig * 16 + lane) * 68 + jg * 16 + q4 * 4] =
            make_float4(vacc[q4*4], vacc[q4*4+1], vacc[q4*4+2], vacc[q4*4+3]);
        *(float4*)&upart[(jg * 16 + lane) * 68 + ig * 16 + q4 * 4] =
            make_float4(uacc[q4*4], uacc[q4*4+1], uacc[q4*4+2], uacc[q4*4+3]);
    }
    __syncthreads();

    // 4-way combine (partials at stride 1088 = 16*68)
    #pragma unroll
    for (int k = 0; k < 4; ++k) {
        int s  = tid + k * 256;            // 0..1023
        int ee = s >> 6, xx = s & 63;
        int o = ee * 68 + xx;
        float a = vpart[o] + vpart[1088 + o] + vpart[2176 + o] + vpart[3264 + o];
        float c = upart[o] + upart[1088 + o] + upart[2176 + o] + upart[3264 + o];
        vs[o] = a;                         // own slot (== vpart[0] copy)
        us[o] = c;
    }
    asm volatile("cp.async.wait_group 0;");
    __syncthreads();

    // ---- Phase 2: f32x2-paired matvec; thread owns e=lane, n = grp*4..+3 ---
    unsigned long long accv[2] = {0ull, 0ull};
    unsigned long long accu[2] = {0ull, 0ull};

    #pragma unroll 4
    for (int j4 = 0; j4 < 16; ++j4) {
        float4 va = *(const float4*)&vs[lane * 68 + j4 * 4];
        float4 ua = *(const float4*)&us[lane * 68 + j4 * 4];
        #pragma unroll
        for (int jj = 0; jj < 4; ++jj) {
            float a  = (&va.x)[jj];
            float bb = (&ua.x)[jj];
            unsigned long long aa = pack2(a, a);
            unsigned long long bp = pack2(bb, bb);
            const float* mrow = &Msh[(j4 * 4 + jj) * 64 + grp * 4];
            #pragma unroll
            for (int p = 0; p < 2; ++p) {
                unsigned long long mm =
                    *(const unsigned long long*)(mrow + p * 2);  // bcast LDS.64
                accv[p] = ffma2(mm, aa, accv[p]);
                accu[p] = ffma2(mm, bp, accu[p]);
            }
        }
    }
    #pragma unroll
    for (int p = 0; p < 2; ++p) {
        float r0, r1, s0, s1;
        unpack2(r0, r1, accv[p]);
        unpack2(s0, s1, accu[p]);
        const int n0 = grp * 4 + p * 2;
        rvs[n0 * 16 + lane]       = r0;
        rvs[(n0 + 1) * 16 + lane] = r1;
        rus[n0 * 16 + lane]       = s0;
        rus[(n0 + 1) * 16 + lane] = s1;
    }
    __syncthreads();

    // ---- z_pb (b==0, eq==0): before phase 3, overlaps chip write phase -----
    if (b == 0 && eq == 0) {
        if (tid < 64) {
            float acc = 0.f;
            #pragma unroll
            for (int j = 0; j < 64; ++j) acc += Msh[j * 64 + tid] * osh[j];
            zp[tid] = 64.0f * acc;
        }
        __syncthreads();
        for (int idx = tid; idx < 4096; idx += 256) {
            int i = idx >> 6, j = idx & 63;
            out2[(size_t)idx * 16 + h] = zp[j] + zp[i];
        }
    }

    // ---- Phase 3: streaming float4 output ----------------------------------
    const int q  = tid & 3;                // float4 slot within 16-e quarter
    const int rg = tid >> 2;               // 0..63 (j)
    float* ob = out + ((size_t)b * STOT * NH + h) * NE + eq * 16;
    float4 a4 = *(const float4*)&rvs[rg * 16 + q * 4];   // j = rg, invariant
    #pragma unroll 4
    for (int r = 0; r < 64; ++r) {         // i = r
        float4 c4 = *(const float4*)&rus[r * 16 + q * 4];
        float4 o4 = make_float4(a4.x + c4.x, a4.y + c4.y, a4.z + c4.z, a4.w + c4.w);
        __stcs((float4*)&ob[((size_t)(r * 64 + rg)) * 1024 + q * 4], o4);
    }
}

// ---------------------------------------------------------------------------
extern "C" void kernel_launch(void* const* d_in, const int* in_sizes, int n_in,
                              void* d_out, int out_size) {
    const float* v  = (const float*)d_in[0];   // (8,4096,16,64) f32
    const float* w  = (const float*)d_in[1];   // (1,16,127) f32
    const float* o_ = (const float*)d_in[2];   // (64,) f32
    float* out  = (float*)d_out;
    float* out2 = out + (size_t)NB * STOT * NH * NE;   // z_pb region

    const int smem_bytes = (4352 * 2 + 4096) * 4;      // 51200 B -> 4 CTAs/SM

    cudaFuncSetAttribute(fftbias_fused,
                         cudaFuncAttributeMaxDynamicSharedMemorySize, smem_bytes);

    fftbias_fused<<<NB * NH * 4, 256, smem_bytes>>>(v, w, o_, out, out2);
}

// round 17
// speedup vs baseline: 1.0906x; 1.0906x over previous
#include <cuda_runtime.h>
#include <cstdint>

// Problem constants: B=8, S=4096, H=16, E=64, s=64
#define NB 8
#define NH 16
#define STOT 4096

#define TWO_PI 6.283185307179586476925f

__device__ float g_Mt[NH * 4096];        // TRANSPOSED operator g_Mt[h][j][n]
__device__ int   g_ready[NH];            // monotone builder counter (16/head)
__device__ int   g_done[256];            // monotone per-(b,h,eh) A-quarter count
__device__ unsigned int g_ticket;        // reset to 0 each launch via memset node
__device__ float g_vs[256][4][2048];     // partial v_s [bh][iq][e*64+j]  (8MB)
__device__ float g_us[256][4][512];      // u_s quarters [bh][iq][e*16+i]  (2MB)

__device__ __forceinline__ uint32_t s2u(const void* p) {
    return (uint32_t)__cvta_generic_to_shared(p);
}
__device__ __forceinline__ void cp16(float* dst, const float* src) {
    asm volatile("cp.async.cg.shared.global [%0], [%1], 16;"
                 :: "r"(s2u(dst)), "l"(src));
}
__device__ __forceinline__ unsigned long long pack2(float x, float y) {
    unsigned long long r;
    asm("mov.b64 %0, {%1, %2};" : "=l"(r) : "f"(x), "f"(y));
    return r;
}
__device__ __forceinline__ void unpack2(float& x, float& y, unsigned long long v) {
    asm("mov.b64 {%0, %1}, %2;" : "=f"(x), "=f"(y) : "l"(v));
}
__device__ __forceinline__ unsigned long long ffma2(unsigned long long m,
                                                    unsigned long long a,
                                                    unsigned long long c) {
    unsigned long long d;
    asm("fma.rn.f32x2 %0, %1, %2, %3;" : "=l"(d) : "l"(m), "l"(a), "l"(c));
    return d;
}

// ---------------------------------------------------------------------------
// Persistent scheduler kernel: grid 296 (2/SM, all co-resident), 512 threads,
// 61.4KB dyn smem.  2048 tickets: t<1024 -> A-unit (stream+reduce a quarter),
// else B-unit (combine quarters, matvec, write rows).  Builders = blocks<256.
// ---------------------------------------------------------------------------
__global__ __launch_bounds__(512, 2)
void fftbias_fused(const float* __restrict__ v,
                   const float* __restrict__ w,
                   const float* __restrict__ o_,
                   float* __restrict__ out,
                   float* __restrict__ out2) {
    const int bx = blockIdx.x;
    const int tid  = threadIdx.x;
    const int lane = tid & 31;             // local e (0..31)
    const int grp  = tid >> 5;             // warp 0..15

    extern __shared__ float sm[];
    float* vpart  = sm;                    // A: [4 ig2][32 e][68]   (8704)
    float* upartU = sm + 8704;             // A: [4 jg][32 e][20]    (2560)
    float* Msh    = sm + 11264;            // B: [64 j][64 n]        (4096)
    // B-path aliases (region A):
    float* vs  = sm;                       // [32][68]  = 2176
    float* rvs = sm + 2176;                // [64][32]  = 2048
    float* rus = sm + 4224;                // [64][32]  = 2048
    float* us  = sm + 8704;                // [32][68]  = 2176 (in region U)
    __shared__ float osh[64];
    __shared__ float zp[64];
    __shared__ unsigned int s_ticket;

    if (tid < 64) osh[tid] = o_[tid];

    // ---- Builder (blocks < 256): 4 n-rows of M_{h_b}, chunk c = bx>>4 ------
    if (bx < 256) {
        const int h_b = bx & 15;
        const int c   = bx >> 4;           // 0..15
        float2* root127 = (float2*)vpart;              // 128 f2
        float2* root126 = root127 + 128;               // 128 f2
        float2* Zpart   = root126 + 128;               // 512 f2
        float2* Zsh     = Zpart + 512;                 // 64 f2
        float2* Ash     = Zsh + 64;                    // 64 f2
        float*  zsh     = (float*)(Ash + 64);          // 128 f
        float2* Psh     = (float2*)(zsh + 128);        // 256 f2
        float*  part    = (float*)(Psh + 256);         // 512 f

        if (tid < 127) {
            float sv, cv;
            __sincosf(TWO_PI * (float)tid / 127.0f, &sv, &cv);
            root127[tid] = make_float2(cv, sv);
            zsh[tid] = w[h_b * 127 + tid];
        }
        if (tid < 126) {
            float sv, cv;
            __sincosf(TWO_PI * (float)tid / 126.0f, &sv, &cv);
            root126[tid] = make_float2(cv, sv);
        }
        __syncthreads();

        {   // Z[k]: 8 u-chunks of 16
            const int k  = tid & 63;
            const int uc = tid >> 6;
            const int u0 = uc * 16;
            int m = (k * u0) % 127;
            float zr = 0.f, zi = 0.f;
            #pragma unroll
            for (int s = 0; s < 16; ++s) {
                int u = u0 + s;
                if (u < 127) {
                    float2 rt = root127[m];
                    float zu = zsh[u];
                    zr += zu * rt.x;
                    zi -= zu * rt.y;
                }
                m += k; if (m >= 127) m -= 127;
            }
            Zpart[uc * 64 + k] = make_float2(zr, zi);
        }
        __syncthreads();
        if (tid < 64) {
            float zr = 0.f, zi = 0.f;
            #pragma unroll
            for (int uc = 0; uc < 8; ++uc) {
                float2 p = Zpart[uc * 64 + tid];
                zr += p.x; zi += p.y;
            }
            float2 r = root127[(63 * tid) % 127];
            float ck = (tid == 0 || tid == 63) ? (1.0f / 126.0f) : (2.0f / 126.0f);
            Ash[tid] = make_float2(ck * (zr * r.x + zi * r.y),
                                   ck * (zi * r.x - zr * r.y));
        }
        __syncthreads();
        if (tid < 256) {                   // P[nl][k] = A[k] * w126^{kn}
            const int k = tid & 63, nl = tid >> 6;
            const int n = c * 4 + nl;
            float2 a = Ash[k];
            float2 f = root126[(k * n) % 126];
            Psh[nl * 64 + k] = make_float2(a.x * f.x - a.y * f.y,
                                           a.x * f.y + a.y * f.x);
        }
        __syncthreads();
        {   // M[n][j], k halved across thread pairs, incremental roots
            const int ent = tid & 255;
            const int kh  = tid >> 8;
            const int nl  = ent >> 6;
            const int j   = ent & 63;
            float2 r  = root127[(kh * 32 * j) % 127];
            float2 mj = root127[j];
            float acc = 0.f;
            const float2* Pp = Psh + nl * 64 + kh * 32;
            #pragma unroll
            for (int kk = 0; kk < 32; ++kk) {
                float2 Pv = Pp[kk];
                acc = fmaf(Pv.x, r.x, acc);
                acc = fmaf(Pv.y, r.y, acc);
                float nx = r.x * mj.x - r.y * mj.y;
                r.y = fmaf(r.x, mj.y, r.y * mj.x);
                r.x = nx;
            }
            part[tid] = acc;
        }
        __syncthreads();
        if (tid < 256) {
            const int nl = tid >> 6, j = tid & 63;
            const int n  = c * 4 + nl;
            g_Mt[h_b * 4096 + j * 64 + n] = part[tid] + part[tid + 256];
        }
        __syncthreads();
        if (tid == 0) {
            asm volatile("red.release.gpu.global.add.s32 [%0], %1;"
                         :: "l"(&g_ready[h_b]), "r"(1) : "memory");
        }
        __syncthreads();
    }

    // ---- Persistent ticket loop --------------------------------------------
    for (;;) {
        if (tid == 0) s_ticket = atomicAdd(&g_ticket, 1u);
        __syncthreads();
        const unsigned int t = s_ticket;
        if (t >= 2048u) break;

        if (t < 1024u) {
            // ============ A-unit: stream+reduce quarter iq of (b,h,eh) ======
            const int bh = (int)(t >> 2);
            const int iq = (int)(t & 3);
            const int b = bh >> 5, h = (bh >> 1) & 15, eh = bh & 1;
            const int jg  = grp & 3;       // 16 j's
            const int ig2 = grp >> 2;      // 4 i's within the quarter
            const float* base =
                v + ((size_t)b * STOT * NH + h) * 64 + eh * 32 + lane;

            float vacc[16], uacc[4];
            #pragma unroll
            for (int k = 0; k < 16; ++k) vacc[k] = 0.f;
            #pragma unroll
            for (int k = 0; k < 4; ++k) uacc[k] = 0.f;

            #pragma unroll
            for (int il = 0; il < 4; ++il) {
                const int i = iq * 16 + ig2 * 4 + il;
                const float* rowp = base + (size_t)(i * 64 + jg * 16) * 1024;
                #pragma unroll
                for (int jl = 0; jl < 16; ++jl) {
                    float x = __ldcs(rowp + (size_t)jl * 1024);
                    vacc[jl] += x;
                    uacc[il] += x;
                }
            }

            #pragma unroll
            for (int q4 = 0; q4 < 4; ++q4)
                *(float4*)&vpart[(ig2 * 32 + lane) * 68 + jg * 16 + q4 * 4] =
                    make_float4(vacc[q4*4], vacc[q4*4+1],
                                vacc[q4*4+2], vacc[q4*4+3]);
            #pragma unroll
            for (int k = 0; k < 4; ++k)
                upartU[(jg * 32 + lane) * 20 + ig2 * 4 + k] = uacc[k];
            __syncthreads();

            // combine 4 ig2 copies -> g_vs (coalesced STG.32)
            #pragma unroll
            for (int k = 0; k < 4; ++k) {
                int s  = tid + k * 512;    // 0..2047 = e*64+j
                int o  = (s >> 6) * 68 + (s & 63);
                float a = vpart[o] + vpart[2176 + o] +
                          vpart[4352 + o] + vpart[6528 + o];
                g_vs[bh][iq][s] = a;
            }
            {   // u_s: 512 values, 1/thread
                int ee = tid >> 4, ii = tid & 15;
                float c = upartU[ee * 20 + ii] + upartU[640 + ee * 20 + ii] +
                          upartU[1280 + ee * 20 + ii] + upartU[1920 + ee * 20 + ii];
                g_us[bh][iq][tid] = c;
            }
            __syncthreads();
            if (tid == 0) {
                asm volatile("red.release.gpu.global.add.s32 [%0], %1;"
                             :: "l"(&g_done[bh]), "r"(1) : "memory");
            }
            __syncthreads();
        } else {
            // ============ B-unit: combine, matvec, write quarter ============
            const unsigned int t2 = t - 1024u;
            const int bh = (int)(t2 >> 2);
            const int iq = (int)(t2 & 3);
            const int b = bh >> 5, h = (bh >> 1) & 15, eh = bh & 1;

            if (tid == 0) {
                int rdy;
                do {
                    asm volatile("ld.acquire.gpu.global.b32 %0, [%1];"
                                 : "=r"(rdy) : "l"(&g_done[bh]) : "memory");
                } while (rdy < 4);
                do {
                    asm volatile("ld.acquire.gpu.global.b32 %0, [%1];"
                                 : "=r"(rdy) : "l"(&g_ready[h]) : "memory");
                } while (rdy < 16);
            }
            __syncthreads();

            {   // M fetch (async, overlaps the combines below)
                const float* Msrc = g_Mt + h * 4096;
                cp16(Msh + tid * 8,     Msrc + tid * 8);
                cp16(Msh + tid * 8 + 4, Msrc + tid * 8 + 4);
                asm volatile("cp.async.commit_group;");
            }

            // vs = sum of 4 quarters (L2-resident)
            #pragma unroll
            for (int k = 0; k < 4; ++k) {
                int s = tid + k * 512;
                float a = g_vs[bh][0][s] + g_vs[bh][1][s] +
                          g_vs[bh][2][s] + g_vs[bh][3][s];
                vs[(s >> 6) * 68 + (s & 63)] = a;
            }
            // us = concat of 4 quarters
            #pragma unroll
            for (int k = 0; k < 4; ++k) {
                int s = tid + k * 512;
                int ee = s >> 6, xx = s & 63;
                us[ee * 68 + xx] = g_us[bh][xx >> 4][ee * 16 + (xx & 15)];
            }
            asm volatile("cp.async.wait_group 0;");
            __syncthreads();

            // matvec (R15 f32x2 path): rv & ru for all 64 n
            unsigned long long accv[2] = {0ull, 0ull};
            unsigned long long accu[2] = {0ull, 0ull};
            #pragma unroll 4
            for (int j4 = 0; j4 < 16; ++j4) {
                float4 va = *(const float4*)&vs[lane * 68 + j4 * 4];
                float4 ua = *(const float4*)&us[lane * 68 + j4 * 4];
                #pragma unroll
                for (int jj = 0; jj < 4; ++jj) {
                    float a  = (&va.x)[jj];
                    float bb = (&ua.x)[jj];
                    unsigned long long aa = pack2(a, a);
                    unsigned long long bp = pack2(bb, bb);
                    const float* mrow = &Msh[(j4 * 4 + jj) * 64 + grp * 4];
                    #pragma unroll
                    for (int p = 0; p < 2; ++p) {
                        unsigned long long mm =
                            *(const unsigned long long*)(mrow + p * 2);
                        accv[p] = ffma2(mm, aa, accv[p]);
                        accu[p] = ffma2(mm, bp, accu[p]);
                    }
                }
            }
            __syncthreads();               // vs/us reads done; rvs/rus overlap
            #pragma unroll
            for (int p = 0; p < 2; ++p) {
                float r0, r1, s0, s1;
                unpack2(r0, r1, accv[p]);
                unpack2(s0, s1, accu[p]);
                const int n0 = grp * 4 + p * 2;
                rvs[n0 * 32 + lane]       = r0;
                rvs[(n0 + 1) * 32 + lane] = r1;
                rus[n0 * 32 + lane]       = s0;
                rus[(n0 + 1) * 32 + lane] = s1;
            }
            __syncthreads();

            // z_pb once per head (b==0, eh==0, iq==0)
            if (b == 0 && eh == 0 && iq == 0) {
                if (tid < 64) {
                    float acc = 0.f;
                    #pragma unroll
                    for (int j = 0; j < 64; ++j)
                        acc += Msh[j * 64 + tid] * osh[j];
                    zp[tid] = 64.0f * acc;
                }
                __syncthreads();
                for (int idx = tid; idx < 4096; idx += 512) {
                    int i = idx >> 6, j = idx & 63;
                    out2[(size_t)idx * 16 + h] = zp[j] + zp[i];
                }
            }

            // phase 3: rows i = iq*16 + r
            const int q  = tid & 7;
            const int rg = tid >> 3;       // j
            float* ob = out + ((size_t)b * STOT * NH + h) * 64 + eh * 32;
            float4 a4 = *(const float4*)&rvs[rg * 32 + q * 4];
            #pragma unroll 4
            for (int r = 0; r < 16; ++r) {
                int i = iq * 16 + r;
                float4 c4 = *(const float4*)&rus[i * 32 + q * 4];
                float4 o4 = make_float4(a4.x + c4.x, a4.y + c4.y,
                                        a4.z + c4.z, a4.w + c4.w);
                __stcs((float4*)&ob[((size_t)(i * 64 + rg)) * 1024 + q * 4], o4);
            }
            __syncthreads();
        }
    }
}

// ---------------------------------------------------------------------------
extern "C" void kernel_launch(void* const* d_in, const int* in_sizes, int n_in,
                              void* d_out, int out_size) {
    const float* v  = (const float*)d_in[0];   // (8,4096,16,64) f32
    const float* w  = (const float*)d_in[1];   // (1,16,127) f32
    const float* o_ = (const float*)d_in[2];   // (64,) f32
    float* out  = (float*)d_out;
    float* out2 = out + (size_t)NB * STOT * NH * 64;   // z_pb region

    // reset the ticket counter each launch (memset node; graph-capturable)
    void* tick = nullptr;
    cudaGetSymbolAddress(&tick, g_ticket);
    cudaMemsetAsync(tick, 0, sizeof(unsigned int));

    const int smem_bytes = 15360 * 4;          // 61440 B -> 2+ CTAs/SM

    cudaFuncSetAttribute(fftbias_fused,
                         cudaFuncAttributeMaxDynamicSharedMemorySize, smem_bytes);

    fftbias_fused<<<296, 512, smem_bytes>>>(v, w, o_, out, out2);
}